// round 7
// baseline (speedup 1.0000x reference)
#include <cuda_runtime.h>
#include <cuda_bf16.h>
#include <math.h>
#include <stdint.h>

// Problem constants
#define BATCH   2
#define SEQ     2048
#define EMB     1024
#define NHEAD   16
#define QKVN    3072
#define MROWS   4096
#define TINY_F  1.17549435e-38f
#define SCALE_Q 0.125f
#define BIGNEG  -9000000000000000.0f
#define BIGPOS   9000000000000000.0f

// Global scratch
__device__ __nv_bfloat16 g_x_hi[(size_t)MROWS * EMB];
__device__ __nv_bfloat16 g_x_lo[(size_t)MROWS * EMB];
__device__ __nv_bfloat16 g_w_hi[(size_t)EMB * QKVN];
__device__ __nv_bfloat16 g_w_lo[(size_t)EMB * QKVN];
__device__ __nv_bfloat16 g_qkv_hi[(size_t)MROWS * QKVN];
__device__ __nv_bfloat16 g_qkv_lo[(size_t)MROWS * QKVN];
__device__ float g_wsc[BATCH * SEQ];
__device__ float g_wvl[BATCH * SEQ];

// ---------------------------------------------------------------------------
// PTX helpers
// ---------------------------------------------------------------------------
#define MMA_BF16(c, a0, a1, a2, a3, b0, b1)                                  \
    asm volatile(                                                            \
        "mma.sync.aligned.m16n8k16.row.col.f32.bf16.bf16.f32 "               \
        "{%0,%1,%2,%3}, {%4,%5,%6,%7}, {%8,%9}, {%0,%1,%2,%3};"              \
        : "+f"((c)[0]), "+f"((c)[1]), "+f"((c)[2]), "+f"((c)[3])             \
        : "r"(a0), "r"(a1), "r"(a2), "r"(a3), "r"(b0), "r"(b1))

#define LDSM_X4(r0, r1, r2, r3, a)                                           \
    asm volatile("ldmatrix.sync.aligned.m8n8.x4.shared.b16 {%0,%1,%2,%3}, [%4];" \
        : "=r"(r0), "=r"(r1), "=r"(r2), "=r"(r3) : "r"(a))

#define LDSM_X4_T(r0, r1, r2, r3, a)                                         \
    asm volatile("ldmatrix.sync.aligned.m8n8.x4.trans.shared.b16 {%0,%1,%2,%3}, [%4];" \
        : "=r"(r0), "=r"(r1), "=r"(r2), "=r"(r3) : "r"(a))

#define CPA16(dst_u32, src_ptr)                                              \
    asm volatile("cp.async.cg.shared.global [%0], [%1], 16;"                 \
                 :: "r"(dst_u32), "l"(src_ptr))
#define CPA_COMMIT() asm volatile("cp.async.commit_group;")
#define CPA_WAIT1()  asm volatile("cp.async.wait_group 1;")
#define CPA_WAIT0()  asm volatile("cp.async.wait_group 0;")

__device__ __forceinline__ void split2(float x, float y,
                                       uint32_t& hi, uint32_t& lo)
{
    __nv_bfloat162 h = __floats2bfloat162_rn(x, y);
    float rx = x - __bfloat162float(h.x);
    float ry = y - __bfloat162float(h.y);
    __nv_bfloat162 l = __floats2bfloat162_rn(rx, ry);
    hi = *reinterpret_cast<uint32_t*>(&h);
    lo = *reinterpret_cast<uint32_t*>(&l);
}

// ---------------------------------------------------------------------------
// Prep kernels
// ---------------------------------------------------------------------------
__device__ __forceinline__ void split_store(const float4* in, uint2* hi,
                                            uint2* lo, int i)
{
    float4 v = in[i];
    uint2 uh, ul;
    split2(v.x, v.y, uh.x, ul.x);
    split2(v.z, v.w, uh.y, ul.y);
    hi[i] = uh;
    lo[i] = ul;
}

__global__ void split_x_kernel(const float4* __restrict__ in)
{
    int i = blockIdx.x * blockDim.x + threadIdx.x;
    if (i < MROWS * EMB / 4)
        split_store(in, (uint2*)g_x_hi, (uint2*)g_x_lo, i);
}

__global__ void split_w_kernel(const float4* __restrict__ in)
{
    int i = blockIdx.x * blockDim.x + threadIdx.x;
    if (i < EMB * QKVN / 4)
        split_store(in, (uint2*)g_w_hi, (uint2*)g_w_lo, i);
}

__global__ void wprep_kernel(const float* __restrict__ w)
{
    int i = blockIdx.x * blockDim.x + threadIdx.x;
    if (i < BATCH * SEQ) {
        const float v = w[i];
        const bool z = (v == 0.0f), on = (v == 1.0f);
        g_wsc[i] = (z || on) ? 0.0f : SCALE_Q;
        g_wvl[i] = z ? BIGNEG : (on ? BIGPOS : logf(v + TINY_F));
    }
}

// ---------------------------------------------------------------------------
// Kernel 1: qkv = x @ W + b, bf16x3 mma. CTA 128x128, BK=32, 256 threads.
// EXACT R4 structure: 2-buffer ring, issue-before-wait (overlaps the LSU
// burst with the previous tile's mma tail).
// ---------------------------------------------------------------------------
#define GA_STR 40
#define GB_STR 136
#define GA_H   (128 * GA_STR)
#define GB_H   (32 * GB_STR)
#define GBUF_H (2 * GA_H + 2 * GB_H)
#define GEMM_SMEM_BYTES (2 * GBUF_H * 2)  // 75776 -> 2 CTAs/SM

__global__ void __launch_bounds__(256)
qkv_gemm(const float* __restrict__ bias)
{
    extern __shared__ __nv_bfloat16 sh[];
    const uint32_t sbase = (uint32_t)__cvta_generic_to_shared(sh);

    const int tid  = threadIdx.x;
    const int lane = tid & 31, wid = tid >> 5;
    const int g = lane >> 2, tig = lane & 3;
    const int wr = wid >> 1, wc = wid & 1;
    const int bn = blockIdx.x * 128, bm = blockIdx.y * 128;

    const uint32_t OAh = 0, OAl = GA_H * 2;
    const uint32_t OBh = 2 * GA_H * 2, OBl = (2 * GA_H + GB_H) * 2;
    const uint32_t BUFB = GBUF_H * 2;

    float acc[2][8][4];
#pragma unroll
    for (int mt = 0; mt < 2; mt++)
#pragma unroll
        for (int j = 0; j < 8; j++)
#pragma unroll
            for (int q = 0; q < 4; q++) acc[mt][j][q] = 0.0f;

    const int a_row = (lane & 7) + 8 * ((lane >> 3) & 1);
    const int a_col = 8 * (lane >> 4);
    const int b_row = lane & 15;
    const int b_col = 8 * (lane >> 4);

#define GEMM_ISSUE(buf, kt)                                                  \
    do {                                                                     \
        const uint32_t sb = sbase + (buf) * BUFB;                            \
        _Pragma("unroll")                                                    \
        for (int i = 0; i < 2; i++) {                                        \
            int ch = tid + 256 * i;                                          \
            int r = ch >> 2, sg = ch & 3;                                    \
            size_t go = (size_t)(bm + r) * EMB + (kt) * 32 + sg * 8;         \
            uint32_t d = sb + (uint32_t)(r * GA_STR + sg * 8) * 2;           \
            CPA16(d + OAh, g_x_hi + go);                                     \
            CPA16(d + OAl, g_x_lo + go);                                     \
        }                                                                    \
        _Pragma("unroll")                                                    \
        for (int i = 0; i < 2; i++) {                                        \
            int ch = tid + 256 * i;                                          \
            int r = ch >> 4, sg = ch & 15;                                   \
            size_t go = (size_t)((kt) * 32 + r) * QKVN + bn + sg * 8;        \
            uint32_t d = sb + (uint32_t)(r * GB_STR + sg * 8) * 2;           \
            CPA16(d + OBh, g_w_hi + go);                                     \
            CPA16(d + OBl, g_w_lo + go);                                     \
        }                                                                    \
    } while (0)

    GEMM_ISSUE(0, 0);
    CPA_COMMIT();

    for (int kt = 0; kt < 32; kt++) {
        const int buf = kt & 1;
        if (kt < 31) {
            GEMM_ISSUE(buf ^ 1, kt + 1);
            CPA_COMMIT();
            CPA_WAIT1();
        } else {
            CPA_WAIT0();
        }
        __syncthreads();

        const uint32_t sb = sbase + buf * BUFB;
#pragma unroll
        for (int ks = 0; ks < 2; ks++) {
            const int k0 = ks * 16;
            uint32_t ah[2][4], al[2][4];
#pragma unroll
            for (int mt = 0; mt < 2; mt++) {
                const uint32_t off =
                    (uint32_t)((wr * 32 + mt * 16 + a_row) * GA_STR + k0 + a_col) * 2;
                LDSM_X4(ah[mt][0], ah[mt][1], ah[mt][2], ah[mt][3], sb + OAh + off);
                LDSM_X4(al[mt][0], al[mt][1], al[mt][2], al[mt][3], sb + OAl + off);
            }
#pragma unroll
            for (int jp = 0; jp < 4; jp++) {
                const uint32_t off =
                    (uint32_t)((k0 + b_row) * GB_STR + wc * 64 + jp * 16 + b_col) * 2;
                uint32_t bh0, bh1, bh2, bh3, bl0, bl1, bl2, bl3;
                LDSM_X4_T(bh0, bh1, bh2, bh3, sb + OBh + off);
                LDSM_X4_T(bl0, bl1, bl2, bl3, sb + OBl + off);
#pragma unroll
                for (int mt = 0; mt < 2; mt++) {
                    MMA_BF16(acc[mt][2 * jp], ah[mt][0], ah[mt][1], ah[mt][2], ah[mt][3], bh0, bh1);
                    MMA_BF16(acc[mt][2 * jp], ah[mt][0], ah[mt][1], ah[mt][2], ah[mt][3], bl0, bl1);
                    MMA_BF16(acc[mt][2 * jp], al[mt][0], al[mt][1], al[mt][2], al[mt][3], bh0, bh1);
                    MMA_BF16(acc[mt][2 * jp + 1], ah[mt][0], ah[mt][1], ah[mt][2], ah[mt][3], bh2, bh3);
                    MMA_BF16(acc[mt][2 * jp + 1], ah[mt][0], ah[mt][1], ah[mt][2], ah[mt][3], bl2, bl3);
                    MMA_BF16(acc[mt][2 * jp + 1], al[mt][0], al[mt][1], al[mt][2], al[mt][3], bh2, bh3);
                }
            }
        }
        __syncthreads();
    }

    // Epilogue
#pragma unroll
    for (int mt = 0; mt < 2; mt++) {
        const int row0 = bm + wr * 32 + mt * 16 + g;
#pragma unroll
        for (int j = 0; j < 8; j++) {
            const int col = bn + wc * 64 + j * 8 + 2 * tig;
            const float2 bb = *(const float2*)(bias + col);
            uint32_t h0, l0, h1, l1;
            split2(acc[mt][j][0] + bb.x, acc[mt][j][1] + bb.y, h0, l0);
            split2(acc[mt][j][2] + bb.x, acc[mt][j][3] + bb.y, h1, l1);
            *(uint32_t*)(g_qkv_hi + (size_t)row0 * QKVN + col)       = h0;
            *(uint32_t*)(g_qkv_lo + (size_t)row0 * QKVN + col)       = l0;
            *(uint32_t*)(g_qkv_hi + (size_t)(row0 + 8) * QKVN + col) = h1;
            *(uint32_t*)(g_qkv_lo + (size_t)(row0 + 8) * QKVN + col) = l1;
        }
    }
#undef GEMM_ISSUE
}

// ---------------------------------------------------------------------------
// Kernel 2: flash attention, bf16x3, delayed-PV pipeline.
// Grid (S/128, H, B), 256 threads. BQ=128, BN=64, 32 tiles.
// 3-slot combined K/V ring: iter t reads K(t)=slot t%3, V(t-1)=slot (t+2)%3,
// writes tile t+1 into slot (t+1)%3 — all distinct; one barrier per tile.
// PV(t-1) mma overlaps softmax(t) ALU/MUFU (independent by construction).
// ---------------------------------------------------------------------------
#define ATS      72
#define QTILE_B  (128 * ATS * 2)               // 18432 per array
#define KT64_B   (64 * ATS * 2)                // 9216 per array
#define BQh      0
#define BQl      QTILE_B
#define KVBASE   (2 * QTILE_B)                 // 36864
#define SLOT_B   (4 * KT64_B)                  // 36864
#define OKh      0
#define OKl      KT64_B
#define OVh      (2 * KT64_B)
#define OVl      (3 * KT64_B)
#define WOFF     (KVBASE + 3 * SLOT_B)         // 147456
#define ATTN_SMEM_BYTES (WOFF + 2 * SEQ * 4)   // 163840
#define NKT      (SEQ / 64)                    // 32

__global__ void __launch_bounds__(256)
attn_bf16(float* __restrict__ out)
{
    extern __shared__ char shb[];
    const uint32_t sb = (uint32_t)__cvta_generic_to_shared(shb);
    const float* swsc = (const float*)(shb + WOFF);
    const float* swvl = swsc + SEQ;

    const int tid  = threadIdx.x;
    const int lane = tid & 31, wrp = tid >> 5;
    const int g = lane >> 2, tig = lane & 3;
    const int qt = blockIdx.x, h = blockIdx.y, b = blockIdx.z;

    const int a_row = (lane & 7) + 8 * ((lane >> 3) & 1);
    const int a_col = 8 * (lane >> 4);
    const int k_row = (lane & 7) + 8 * (lane >> 4);
    const int k_col = 8 * ((lane >> 3) & 1);

    // 64 keys: 512 16B-chunks per array -> 2 per thread per array
#define KV_ISSUE(slot, tt)                                                   \
    do {                                                                     \
        const uint32_t kbase = sb + KVBASE + (uint32_t)(slot) * SLOT_B;      \
        _Pragma("unroll")                                                    \
        for (int i = 0; i < 2; i++) {                                        \
            int ch = tid + 256 * i;                                          \
            int r = ch >> 3, sg = ch & 7;                                    \
            size_t go = (size_t)(b * SEQ + (tt) * 64 + r) * QKVN + h * 192 + sg * 8; \
            uint32_t d = (uint32_t)(r * ATS + sg * 8) * 2;                   \
            CPA16(kbase + OKh + d, g_qkv_hi + go + 64);                      \
            CPA16(kbase + OKl + d, g_qkv_lo + go + 64);                      \
            CPA16(kbase + OVh + d, g_qkv_hi + go + 128);                     \
            CPA16(kbase + OVl + d, g_qkv_lo + go + 128);                     \
        }                                                                    \
        CPA_COMMIT();                                                        \
    } while (0)

    // ---- prologue: Q + w (group 0), KV tile 0 (group 1) ----
#pragma unroll
    for (int i = 0; i < 4; i++) {
        const int ch = tid + 256 * i;
        const int r = ch >> 3, sg = ch & 7;
        const size_t go = (size_t)(b * SEQ + qt * 128 + r) * QKVN + h * 192 + sg * 8;
        const uint32_t d = (uint32_t)(r * ATS + sg * 8) * 2;
        CPA16(sb + BQh + d, g_qkv_hi + go);
        CPA16(sb + BQl + d, g_qkv_lo + go);
    }
#pragma unroll
    for (int i = 0; i < 2; i++) {
        const int ch = tid + 256 * i;
        CPA16(sb + WOFF + ch * 16, g_wsc + b * SEQ + ch * 4);
        CPA16(sb + WOFF + SEQ * 4 + ch * 16, g_wvl + b * SEQ + ch * 4);
    }
    CPA_COMMIT();
    KV_ISSUE(0, 0);
    CPA_WAIT1();           // Q + w landed
    __syncthreads();

    // Q fragments -> registers (loop invariant)
    uint32_t qh[4][4], ql[4][4];
#pragma unroll
    for (int kk = 0; kk < 4; kk++) {
        const uint32_t off =
            (uint32_t)((16 * wrp + a_row) * ATS + kk * 16 + a_col) * 2;
        LDSM_X4(qh[kk][0], qh[kk][1], qh[kk][2], qh[kk][3], sb + BQh + off);
        LDSM_X4(ql[kk][0], ql[kk][1], ql[kk][2], ql[kk][3], sb + BQl + off);
    }

    float m0 = -1e30f, m1 = -1e30f, l0 = 0.0f, l1 = 0.0f;
    float o[8][4];
#pragma unroll
    for (int j = 0; j < 8; j++)
        o[j][0] = o[j][1] = o[j][2] = o[j][3] = 0.0f;

    uint32_t pph[4][4], ppl[4][4];    // packed P of previous tile

    for (int t = 0; t < NKT; t++) {
        const int slot = t % 3;
        CPA_WAIT0();        // tile t landed (sole pending group)
        __syncthreads();    // readers of slot (t+1)%3 (tiles t-2 K / V) done

        if (t + 1 < NKT)
            KV_ISSUE((t + 1) % 3, t + 1);

        const uint32_t kb = sb + KVBASE + (uint32_t)slot * SLOT_B;

        // ---- S = Q K^T : 16 q-rows x 64 keys per warp (bf16x3) ----
        float s[8][4];
#pragma unroll
        for (int j = 0; j < 8; j++)
            s[j][0] = s[j][1] = s[j][2] = s[j][3] = 0.0f;

#pragma unroll
        for (int kk = 0; kk < 4; kk++) {
#pragma unroll
            for (int jp = 0; jp < 4; jp++) {
                const uint32_t off =
                    (uint32_t)((jp * 16 + k_row) * ATS + kk * 16 + k_col) * 2;
                uint32_t kh0, kh1, kh2, kh3, kl0, kl1, kl2, kl3;
                LDSM_X4(kh0, kh1, kh2, kh3, kb + OKh + off);
                LDSM_X4(kl0, kl1, kl2, kl3, kb + OKl + off);
                MMA_BF16(s[2 * jp],     qh[kk][0], qh[kk][1], qh[kk][2], qh[kk][3], kh0, kh1);
                MMA_BF16(s[2 * jp],     qh[kk][0], qh[kk][1], qh[kk][2], qh[kk][3], kl0, kl1);
                MMA_BF16(s[2 * jp],     ql[kk][0], ql[kk][1], ql[kk][2], ql[kk][3], kh0, kh1);
                MMA_BF16(s[2 * jp + 1], qh[kk][0], qh[kk][1], qh[kk][2], qh[kk][3], kh2, kh3);
                MMA_BF16(s[2 * jp + 1], qh[kk][0], qh[kk][1], qh[kk][2], qh[kk][3], kl2, kl3);
                MMA_BF16(s[2 * jp + 1], ql[kk][0], ql[kk][1], ql[kk][2], ql[kk][3], kh2, kh3);
            }
        }

        // ---- logit transform + row max (needs only s) ----
        const int wbase = t * 64;
        float mx0 = -1e30f, mx1 = -1e30f;
#pragma unroll
        for (int j = 0; j < 8; j++) {
            const float2 ws = *(const float2*)&swsc[wbase + j * 8 + 2 * tig];
            const float2 wv = *(const float2*)&swvl[wbase + j * 8 + 2 * tig];
            s[j][0] = fmaf(s[j][0], ws.x, wv.x);
            s[j][1] = fmaf(s[j][1], ws.y, wv.y);
            s[j][2] = fmaf(s[j][2], ws.x, wv.x);
            s[j][3] = fmaf(s[j][3], ws.y, wv.y);
            mx0 = fmaxf(mx0, fmaxf(s[j][0], s[j][1]));
            mx1 = fmaxf(mx1, fmaxf(s[j][2], s[j][3]));
        }
        mx0 = fmaxf(mx0, __shfl_xor_sync(0xffffffffu, mx0, 1));
        mx0 = fmaxf(mx0, __shfl_xor_sync(0xffffffffu, mx0, 2));
        mx1 = fmaxf(mx1, __shfl_xor_sync(0xffffffffu, mx1, 1));
        mx1 = fmaxf(mx1, __shfl_xor_sync(0xffffffffu, mx1, 2));

        const float mn0 = fmaxf(m0, mx0), mn1 = fmaxf(m1, mx1);
        const float c0 = __expf(m0 - mn0), c1 = __expf(m1 - mn1);
        m0 = mn0; m1 = mn1;

        // ---- PV(t-1): tensor work independent of the softmax above; the
        //      scheduler overlaps it with the exp/sum below ----
        if (t > 0) {
            const uint32_t vb = sb + KVBASE + (uint32_t)((t + 2) % 3) * SLOT_B;
#pragma unroll
            for (int kk = 0; kk < 4; kk++) {
#pragma unroll
                for (int jp = 0; jp < 4; jp++) {
                    const uint32_t off =
                        (uint32_t)((kk * 16 + a_row) * ATS + jp * 16 + a_col) * 2;
                    uint32_t vh0, vh1, vh2, vh3, vl0, vl1, vl2, vl3;
                    LDSM_X4_T(vh0, vh1, vh2, vh3, vb + OVh + off);
                    LDSM_X4_T(vl0, vl1, vl2, vl3, vb + OVl + off);
                    MMA_BF16(o[2 * jp],     pph[kk][0], pph[kk][1], pph[kk][2], pph[kk][3], vh0, vh1);
                    MMA_BF16(o[2 * jp],     pph[kk][0], pph[kk][1], pph[kk][2], pph[kk][3], vl0, vl1);
                    MMA_BF16(o[2 * jp],     ppl[kk][0], ppl[kk][1], ppl[kk][2], ppl[kk][3], vh0, vh1);
                    MMA_BF16(o[2 * jp + 1], pph[kk][0], pph[kk][1], pph[kk][2], pph[kk][3], vh2, vh3);
                    MMA_BF16(o[2 * jp + 1], pph[kk][0], pph[kk][1], pph[kk][2], pph[kk][3], vl2, vl3);
                    MMA_BF16(o[2 * jp + 1], ppl[kk][0], ppl[kk][1], ppl[kk][2], ppl[kk][3], vh2, vh3);
                }
            }
        }

        // ---- exp + row sums (independent of PV above) ----
        float rs0 = 0.0f, rs1 = 0.0f;
#pragma unroll
        for (int j = 0; j < 8; j++) {
            s[j][0] = __expf(s[j][0] - m0);
            s[j][1] = __expf(s[j][1] - m0);
            s[j][2] = __expf(s[j][2] - m1);
            s[j][3] = __expf(s[j][3] - m1);
            rs0 += s[j][0] + s[j][1];
            rs1 += s[j][2] + s[j][3];
        }
        rs0 += __shfl_xor_sync(0xffffffffu, rs0, 1);
        rs0 += __shfl_xor_sync(0xffffffffu, rs0, 2);
        rs1 += __shfl_xor_sync(0xffffffffu, rs1, 1);
        rs1 += __shfl_xor_sync(0xffffffffu, rs1, 2);

        l0 = l0 * c0 + rs0;
        l1 = l1 * c1 + rs1;

        // ---- o scale (after PV(t-1) accumulated) + pack p(t) ----
#pragma unroll
        for (int j = 0; j < 8; j++) {
            o[j][0] *= c0; o[j][1] *= c0;
            o[j][2] *= c1; o[j][3] *= c1;
        }
#pragma unroll
        for (int kk = 0; kk < 4; kk++) {
            split2(s[2 * kk][0],     s[2 * kk][1],     pph[kk][0], ppl[kk][0]);
            split2(s[2 * kk][2],     s[2 * kk][3],     pph[kk][1], ppl[kk][1]);
            split2(s[2 * kk + 1][0], s[2 * kk + 1][1], pph[kk][2], ppl[kk][2]);
            split2(s[2 * kk + 1][2], s[2 * kk + 1][3], pph[kk][3], ppl[kk][3]);
        }
    }

    // ---- final PV for tile NKT-1 (V slot (NKT-1)%3 still intact) ----
    {
        const uint32_t vb = sb + KVBASE + (uint32_t)((NKT - 1) % 3) * SLOT_B;
#pragma unroll
        for (int kk = 0; kk < 4; kk++) {
#pragma unroll
            for (int jp = 0; jp < 4; jp++) {
                const uint32_t off =
                    (uint32_t)((kk * 16 + a_row) * ATS + jp * 16 + a_col) * 2;
                uint32_t vh0, vh1, vh2, vh3, vl0, vl1, vl2, vl3;
                LDSM_X4_T(vh0, vh1, vh2, vh3, vb + OVh + off);
                LDSM_X4_T(vl0, vl1, vl2, vl3, vb + OVl + off);
                MMA_BF16(o[2 * jp],     pph[kk][0], pph[kk][1], pph[kk][2], pph[kk][3], vh0, vh1);
                MMA_BF16(o[2 * jp],     pph[kk][0], pph[kk][1], pph[kk][2], pph[kk][3], vl0, vl1);
                MMA_BF16(o[2 * jp],     ppl[kk][0], ppl[kk][1], ppl[kk][2], ppl[kk][3], vh0, vh1);
                MMA_BF16(o[2 * jp + 1], pph[kk][0], pph[kk][1], pph[kk][2], pph[kk][3], vh2, vh3);
                MMA_BF16(o[2 * jp + 1], pph[kk][0], pph[kk][1], pph[kk][2], pph[kk][3], vl2, vl3);
                MMA_BF16(o[2 * jp + 1], ppl[kk][0], ppl[kk][1], ppl[kk][2], ppl[kk][3], vh2, vh3);
            }
        }
    }

    // ---- epilogue ----
    const float i0 = 1.0f / l0, i1 = 1.0f / l1;
    const int grow = b * SEQ + qt * 128 + 16 * wrp + g;
#pragma unroll
    for (int j = 0; j < 8; j++) {
        const int col = h * 64 + j * 8 + 2 * tig;
        *(float2*)(out + (size_t)grow * EMB + col) =
            make_float2(o[j][0] * i0, o[j][1] * i0);
        *(float2*)(out + (size_t)(grow + 8) * EMB + col) =
            make_float2(o[j][2] * i1, o[j][3] * i1);
    }
#undef KV_ISSUE
}

// ---------------------------------------------------------------------------
extern "C" void kernel_launch(void* const* d_in, const int* in_sizes, int n_in,
                              void* d_out, int out_size)
{
    const float* x    = (const float*)d_in[0];
    const float* w    = (const float*)d_in[1];
    const float* Wqkv = (const float*)d_in[2];
    const float* bqkv = (const float*)d_in[3];
    float* out = (float*)d_out;

    cudaFuncSetAttribute(qkv_gemm,
                         cudaFuncAttributeMaxDynamicSharedMemorySize,
                         GEMM_SMEM_BYTES);
    cudaFuncSetAttribute(attn_bf16,
                         cudaFuncAttributeMaxDynamicSharedMemorySize,
                         ATTN_SMEM_BYTES);

    split_x_kernel<<<MROWS * EMB / 4 / 256, 256>>>((const float4*)x);
    split_w_kernel<<<EMB * QKVN / 4 / 256, 256>>>((const float4*)Wqkv);
    wprep_kernel<<<(BATCH * SEQ + 255) / 256, 256>>>(w);

    dim3 g1(QKVN / 128, MROWS / 128);            // (24, 32)
    qkv_gemm<<<g1, 256, GEMM_SMEM_BYTES>>>(bqkv);

    dim3 g2(SEQ / 128, NHEAD, BATCH);            // (16, 16, 2)
    attn_bf16<<<g2, 256, ATTN_SMEM_BYTES>>>(out);
}

// round 8
// speedup vs baseline: 1.0672x; 1.0672x over previous
#include <cuda_runtime.h>
#include <cuda_bf16.h>
#include <math.h>
#include <stdint.h>

// Problem constants
#define BATCH   2
#define SEQ     2048
#define EMB     1024
#define NHEAD   16
#define QKVN    3072
#define MROWS   4096
#define TINY_F  1.17549435e-38f
#define SCALE_Q 0.125f
#define LOG2E   1.4426950408889634f
#define BIGNEG2 -1.3e16f
#define BIGPOS2  1.3e16f

// Global scratch
__device__ __nv_bfloat16 g_x_hi[(size_t)MROWS * EMB];
__device__ __nv_bfloat16 g_x_lo[(size_t)MROWS * EMB];
__device__ __nv_bfloat16 g_w_hi[(size_t)EMB * QKVN];
__device__ __nv_bfloat16 g_w_lo[(size_t)EMB * QKVN];
__device__ __nv_bfloat16 g_qkv_hi[(size_t)MROWS * QKVN];
__device__ __nv_bfloat16 g_qkv_lo[(size_t)MROWS * QKVN];
__device__ float g_wsc[BATCH * SEQ];   // log2-domain scale (0 or 0.125*log2e)
__device__ float g_wvl[BATCH * SEQ];   // log2-domain bias

// ---------------------------------------------------------------------------
// PTX helpers
// ---------------------------------------------------------------------------
#define MMA_BF16(c, a0, a1, a2, a3, b0, b1)                                  \
    asm volatile(                                                            \
        "mma.sync.aligned.m16n8k16.row.col.f32.bf16.bf16.f32 "               \
        "{%0,%1,%2,%3}, {%4,%5,%6,%7}, {%8,%9}, {%0,%1,%2,%3};"              \
        : "+f"((c)[0]), "+f"((c)[1]), "+f"((c)[2]), "+f"((c)[3])             \
        : "r"(a0), "r"(a1), "r"(a2), "r"(a3), "r"(b0), "r"(b1))

#define LDSM_X4(r0, r1, r2, r3, a)                                           \
    asm volatile("ldmatrix.sync.aligned.m8n8.x4.shared.b16 {%0,%1,%2,%3}, [%4];" \
        : "=r"(r0), "=r"(r1), "=r"(r2), "=r"(r3) : "r"(a))

#define LDSM_X4_T(r0, r1, r2, r3, a)                                         \
    asm volatile("ldmatrix.sync.aligned.m8n8.x4.trans.shared.b16 {%0,%1,%2,%3}, [%4];" \
        : "=r"(r0), "=r"(r1), "=r"(r2), "=r"(r3) : "r"(a))

#define CPA16(dst_u32, src_ptr)                                              \
    asm volatile("cp.async.cg.shared.global [%0], [%1], 16;"                 \
                 :: "r"(dst_u32), "l"(src_ptr))
#define CPA_COMMIT() asm volatile("cp.async.commit_group;")
#define CPA_WAIT1()  asm volatile("cp.async.wait_group 1;")
#define CPA_WAIT0()  asm volatile("cp.async.wait_group 0;")

__device__ __forceinline__ void split2(float x, float y,
                                       uint32_t& hi, uint32_t& lo)
{
    __nv_bfloat162 h = __floats2bfloat162_rn(x, y);
    float rx = x - __bfloat162float(h.x);
    float ry = y - __bfloat162float(h.y);
    __nv_bfloat162 l = __floats2bfloat162_rn(rx, ry);
    hi = *reinterpret_cast<uint32_t*>(&h);
    lo = *reinterpret_cast<uint32_t*>(&l);
}

// ---------------------------------------------------------------------------
// Prep kernels
// ---------------------------------------------------------------------------
__device__ __forceinline__ void split_store(const float4* in, uint2* hi,
                                            uint2* lo, int i)
{
    float4 v = in[i];
    uint2 uh, ul;
    split2(v.x, v.y, uh.x, ul.x);
    split2(v.z, v.w, uh.y, ul.y);
    hi[i] = uh;
    lo[i] = ul;
}

__global__ void split_x_kernel(const float4* __restrict__ in)
{
    int i = blockIdx.x * blockDim.x + threadIdx.x;
    if (i < MROWS * EMB / 4)
        split_store(in, (uint2*)g_x_hi, (uint2*)g_x_lo, i);
}

__global__ void split_w_kernel(const float4* __restrict__ in)
{
    int i = blockIdx.x * blockDim.x + threadIdx.x;
    if (i < EMB * QKVN / 4)
        split_store(in, (uint2*)g_w_hi, (uint2*)g_w_lo, i);
}

__global__ void wprep_kernel(const float* __restrict__ w)
{
    int i = blockIdx.x * blockDim.x + threadIdx.x;
    if (i < BATCH * SEQ) {
        const float v = w[i];
        const bool z = (v == 0.0f), on = (v == 1.0f);
        g_wsc[i] = (z || on) ? 0.0f : SCALE_Q * LOG2E;
        g_wvl[i] = z ? BIGNEG2 : (on ? BIGPOS2 : log2f(v + TINY_F));
    }
}

// ---------------------------------------------------------------------------
// Kernel 1: qkv = x @ W + b, bf16x3 mma. CTA 128x128, BK=32, 256 threads.
// R4 structure: 2-buffer ring, issue-before-wait.
// ---------------------------------------------------------------------------
#define GA_STR 40
#define GB_STR 136
#define GA_H   (128 * GA_STR)
#define GB_H   (32 * GB_STR)
#define GBUF_H (2 * GA_H + 2 * GB_H)
#define GEMM_SMEM_BYTES (2 * GBUF_H * 2)  // 75776 -> 2 CTAs/SM

__global__ void __launch_bounds__(256)
qkv_gemm(const float* __restrict__ bias)
{
    extern __shared__ __nv_bfloat16 sh[];
    const uint32_t sbase = (uint32_t)__cvta_generic_to_shared(sh);

    const int tid  = threadIdx.x;
    const int lane = tid & 31, wid = tid >> 5;
    const int g = lane >> 2, tig = lane & 3;
    const int wr = wid >> 1, wc = wid & 1;
    const int bn = blockIdx.x * 128, bm = blockIdx.y * 128;

    const uint32_t OAh = 0, OAl = GA_H * 2;
    const uint32_t OBh = 2 * GA_H * 2, OBl = (2 * GA_H + GB_H) * 2;
    const uint32_t BUFB = GBUF_H * 2;

    float acc[2][8][4];
#pragma unroll
    for (int mt = 0; mt < 2; mt++)
#pragma unroll
        for (int j = 0; j < 8; j++)
#pragma unroll
            for (int q = 0; q < 4; q++) acc[mt][j][q] = 0.0f;

    const int a_row = (lane & 7) + 8 * ((lane >> 3) & 1);
    const int a_col = 8 * (lane >> 4);
    const int b_row = lane & 15;
    const int b_col = 8 * (lane >> 4);

#define GEMM_ISSUE(buf, kt)                                                  \
    do {                                                                     \
        const uint32_t sb = sbase + (buf) * BUFB;                            \
        _Pragma("unroll")                                                    \
        for (int i = 0; i < 2; i++) {                                        \
            int ch = tid + 256 * i;                                          \
            int r = ch >> 2, sg = ch & 3;                                    \
            size_t go = (size_t)(bm + r) * EMB + (kt) * 32 + sg * 8;         \
            uint32_t d = sb + (uint32_t)(r * GA_STR + sg * 8) * 2;           \
            CPA16(d + OAh, g_x_hi + go);                                     \
            CPA16(d + OAl, g_x_lo + go);                                     \
        }                                                                    \
        _Pragma("unroll")                                                    \
        for (int i = 0; i < 2; i++) {                                        \
            int ch = tid + 256 * i;                                          \
            int r = ch >> 4, sg = ch & 15;                                   \
            size_t go = (size_t)((kt) * 32 + r) * QKVN + bn + sg * 8;        \
            uint32_t d = sb + (uint32_t)(r * GB_STR + sg * 8) * 2;           \
            CPA16(d + OBh, g_w_hi + go);                                     \
            CPA16(d + OBl, g_w_lo + go);                                     \
        }                                                                    \
    } while (0)

    GEMM_ISSUE(0, 0);
    CPA_COMMIT();

    for (int kt = 0; kt < 32; kt++) {
        const int buf = kt & 1;
        if (kt < 31) {
            GEMM_ISSUE(buf ^ 1, kt + 1);
            CPA_COMMIT();
            CPA_WAIT1();
        } else {
            CPA_WAIT0();
        }
        __syncthreads();

        const uint32_t sb = sbase + buf * BUFB;
#pragma unroll
        for (int ks = 0; ks < 2; ks++) {
            const int k0 = ks * 16;
            uint32_t ah[2][4], al[2][4];
#pragma unroll
            for (int mt = 0; mt < 2; mt++) {
                const uint32_t off =
                    (uint32_t)((wr * 32 + mt * 16 + a_row) * GA_STR + k0 + a_col) * 2;
                LDSM_X4(ah[mt][0], ah[mt][1], ah[mt][2], ah[mt][3], sb + OAh + off);
                LDSM_X4(al[mt][0], al[mt][1], al[mt][2], al[mt][3], sb + OAl + off);
            }
#pragma unroll
            for (int jp = 0; jp < 4; jp++) {
                const uint32_t off =
                    (uint32_t)((k0 + b_row) * GB_STR + wc * 64 + jp * 16 + b_col) * 2;
                uint32_t bh0, bh1, bh2, bh3, bl0, bl1, bl2, bl3;
                LDSM_X4_T(bh0, bh1, bh2, bh3, sb + OBh + off);
                LDSM_X4_T(bl0, bl1, bl2, bl3, sb + OBl + off);
#pragma unroll
                for (int mt = 0; mt < 2; mt++) {
                    MMA_BF16(acc[mt][2 * jp], ah[mt][0], ah[mt][1], ah[mt][2], ah[mt][3], bh0, bh1);
                    MMA_BF16(acc[mt][2 * jp], ah[mt][0], ah[mt][1], ah[mt][2], ah[mt][3], bl0, bl1);
                    MMA_BF16(acc[mt][2 * jp], al[mt][0], al[mt][1], al[mt][2], al[mt][3], bh0, bh1);
                    MMA_BF16(acc[mt][2 * jp + 1], ah[mt][0], ah[mt][1], ah[mt][2], ah[mt][3], bh2, bh3);
                    MMA_BF16(acc[mt][2 * jp + 1], ah[mt][0], ah[mt][1], ah[mt][2], ah[mt][3], bl2, bl3);
                    MMA_BF16(acc[mt][2 * jp + 1], al[mt][0], al[mt][1], al[mt][2], al[mt][3], bh2, bh3);
                }
            }
        }
        __syncthreads();
    }

    // Epilogue
#pragma unroll
    for (int mt = 0; mt < 2; mt++) {
        const int row0 = bm + wr * 32 + mt * 16 + g;
#pragma unroll
        for (int j = 0; j < 8; j++) {
            const int col = bn + wc * 64 + j * 8 + 2 * tig;
            const float2 bb = *(const float2*)(bias + col);
            uint32_t h0, l0, h1, l1;
            split2(acc[mt][j][0] + bb.x, acc[mt][j][1] + bb.y, h0, l0);
            split2(acc[mt][j][2] + bb.x, acc[mt][j][3] + bb.y, h1, l1);
            *(uint32_t*)(g_qkv_hi + (size_t)row0 * QKVN + col)       = h0;
            *(uint32_t*)(g_qkv_lo + (size_t)row0 * QKVN + col)       = l0;
            *(uint32_t*)(g_qkv_hi + (size_t)(row0 + 8) * QKVN + col) = h1;
            *(uint32_t*)(g_qkv_lo + (size_t)(row0 + 8) * QKVN + col) = l1;
        }
    }
#undef GEMM_ISSUE
}

// ---------------------------------------------------------------------------
// Kernel 2: flash attention, bf16x3. Grid (S/128, H, B), 256 threads.
// BQ=128, BN=64, 2-slot KV ring, smem 110592 -> 2 CTAs/SM (4 warps/SMSP).
// w logit coefs read from gmem (L1-resident, broadcast). exp2 domain.
// Q-lo fragments reloaded per tile (register budget for 2-CTA residency).
// ---------------------------------------------------------------------------
#define ATS      72
#define QTILE_B  (128 * ATS * 2)               // 18432 per array
#define KT64_B   (64 * ATS * 2)                // 9216 per array
#define BQh      0
#define BQl      QTILE_B
#define KVBASE   (2 * QTILE_B)                 // 36864
#define SLOT_B   (4 * KT64_B)                  // 36864
#define OKh      0
#define OKl      KT64_B
#define OVh      (2 * KT64_B)
#define OVl      (3 * KT64_B)
#define ATTN_SMEM_BYTES (KVBASE + 2 * SLOT_B)  // 110592
#define NKT      (SEQ / 64)                    // 32

__global__ void __launch_bounds__(256, 2)
attn_bf16(float* __restrict__ out)
{
    extern __shared__ char shb[];
    const uint32_t sb = (uint32_t)__cvta_generic_to_shared(shb);

    const int tid  = threadIdx.x;
    const int lane = tid & 31, wrp = tid >> 5;
    const int g = lane >> 2, tig = lane & 3;
    const int qt = blockIdx.x, h = blockIdx.y, b = blockIdx.z;

    const int a_row = (lane & 7) + 8 * ((lane >> 3) & 1);
    const int a_col = 8 * (lane >> 4);
    const int k_row = (lane & 7) + 8 * (lane >> 4);
    const int k_col = 8 * ((lane >> 3) & 1);

#define KV_ISSUE(slot, tt)                                                   \
    do {                                                                     \
        const uint32_t kbase = sb + KVBASE + (uint32_t)(slot) * SLOT_B;      \
        _Pragma("unroll")                                                    \
        for (int i = 0; i < 2; i++) {                                        \
            int ch = tid + 256 * i;                                          \
            int r = ch >> 3, sg = ch & 7;                                    \
            size_t go = (size_t)(b * SEQ + (tt) * 64 + r) * QKVN + h * 192 + sg * 8; \
            uint32_t d = (uint32_t)(r * ATS + sg * 8) * 2;                   \
            CPA16(kbase + OKh + d, g_qkv_hi + go + 64);                      \
            CPA16(kbase + OKl + d, g_qkv_lo + go + 64);                      \
            CPA16(kbase + OVh + d, g_qkv_hi + go + 128);                     \
            CPA16(kbase + OVl + d, g_qkv_lo + go + 128);                     \
        }                                                                    \
        CPA_COMMIT();                                                        \
    } while (0)

    // ---- prologue: Q (group 0), KV tile 0 (group 1) ----
#pragma unroll
    for (int i = 0; i < 4; i++) {
        const int ch = tid + 256 * i;
        const int r = ch >> 3, sg = ch & 7;
        const size_t go = (size_t)(b * SEQ + qt * 128 + r) * QKVN + h * 192 + sg * 8;
        const uint32_t d = (uint32_t)(r * ATS + sg * 8) * 2;
        CPA16(sb + BQh + d, g_qkv_hi + go);
        CPA16(sb + BQl + d, g_qkv_lo + go);
    }
    CPA_COMMIT();
    KV_ISSUE(0, 0);
    CPA_WAIT1();           // Q landed
    __syncthreads();

    // Q-hi fragments -> registers (loop invariant); Q-lo reloaded per tile
    uint32_t qh[4][4];
#pragma unroll
    for (int kk = 0; kk < 4; kk++) {
        const uint32_t off =
            (uint32_t)((16 * wrp + a_row) * ATS + kk * 16 + a_col) * 2;
        LDSM_X4(qh[kk][0], qh[kk][1], qh[kk][2], qh[kk][3], sb + BQh + off);
    }

    float m0 = -1e30f, m1 = -1e30f, l0 = 0.0f, l1 = 0.0f;
    float o[8][4];
#pragma unroll
    for (int j = 0; j < 8; j++)
        o[j][0] = o[j][1] = o[j][2] = o[j][3] = 0.0f;

    const float* wscp = g_wsc + b * SEQ;
    const float* wvlp = g_wvl + b * SEQ;

    for (int t = 0; t < NKT; t++) {
        const int slot = t & 1;
        CPA_WAIT0();        // tile t landed (sole pending group)
        __syncthreads();    // readers of slot^1 (tile t-1) all done

        if (t + 1 < NKT)
            KV_ISSUE(slot ^ 1, t + 1);

        const uint32_t kb = sb + KVBASE + (uint32_t)slot * SLOT_B;

        // ---- S = Q K^T : 16 q-rows x 64 keys per warp (bf16x3) ----
        float s[8][4];
#pragma unroll
        for (int j = 0; j < 8; j++)
            s[j][0] = s[j][1] = s[j][2] = s[j][3] = 0.0f;

#pragma unroll
        for (int kk = 0; kk < 4; kk++) {
            uint32_t ql0, ql1, ql2, ql3;
            const uint32_t qoff =
                (uint32_t)((16 * wrp + a_row) * ATS + kk * 16 + a_col) * 2;
            LDSM_X4(ql0, ql1, ql2, ql3, sb + BQl + qoff);
#pragma unroll
            for (int jp = 0; jp < 4; jp++) {
                const uint32_t off =
                    (uint32_t)((jp * 16 + k_row) * ATS + kk * 16 + k_col) * 2;
                uint32_t kh0, kh1, kh2, kh3, kl0, kl1, kl2, kl3;
                LDSM_X4(kh0, kh1, kh2, kh3, kb + OKh + off);
                LDSM_X4(kl0, kl1, kl2, kl3, kb + OKl + off);
                MMA_BF16(s[2 * jp],     qh[kk][0], qh[kk][1], qh[kk][2], qh[kk][3], kh0, kh1);
                MMA_BF16(s[2 * jp],     qh[kk][0], qh[kk][1], qh[kk][2], qh[kk][3], kl0, kl1);
                MMA_BF16(s[2 * jp],     ql0, ql1, ql2, ql3, kh0, kh1);
                MMA_BF16(s[2 * jp + 1], qh[kk][0], qh[kk][1], qh[kk][2], qh[kk][3], kh2, kh3);
                MMA_BF16(s[2 * jp + 1], qh[kk][0], qh[kk][1], qh[kk][2], qh[kk][3], kl2, kl3);
                MMA_BF16(s[2 * jp + 1], ql0, ql1, ql2, ql3, kh2, kh3);
            }
        }

        // ---- logit transform (log2 domain, coefs from gmem/L1) + row max ----
        const int wbase = t * 64;
        float mx0 = -1e30f, mx1 = -1e30f;
#pragma unroll
        for (int j = 0; j < 8; j++) {
            const float2 ws = *(const float2*)&wscp[wbase + j * 8 + 2 * tig];
            const float2 wv = *(const float2*)&wvlp[wbase + j * 8 + 2 * tig];
            s[j][0] = fmaf(s[j][0], ws.x, wv.x);
            s[j][1] = fmaf(s[j][1], ws.y, wv.y);
            s[j][2] = fmaf(s[j][2], ws.x, wv.x);
            s[j][3] = fmaf(s[j][3], ws.y, wv.y);
            mx0 = fmaxf(mx0, fmaxf(s[j][0], s[j][1]));
            mx1 = fmaxf(mx1, fmaxf(s[j][2], s[j][3]));
        }
        mx0 = fmaxf(mx0, __shfl_xor_sync(0xffffffffu, mx0, 1));
        mx0 = fmaxf(mx0, __shfl_xor_sync(0xffffffffu, mx0, 2));
        mx1 = fmaxf(mx1, __shfl_xor_sync(0xffffffffu, mx1, 1));
        mx1 = fmaxf(mx1, __shfl_xor_sync(0xffffffffu, mx1, 2));

        const float mn0 = fmaxf(m0, mx0), mn1 = fmaxf(m1, mx1);
        const float c0 = exp2f(m0 - mn0), c1 = exp2f(m1 - mn1);
        m0 = mn0; m1 = mn1;

        float rs0 = 0.0f, rs1 = 0.0f;
#pragma unroll
        for (int j = 0; j < 8; j++) {
            s[j][0] = exp2f(s[j][0] - m0);
            s[j][1] = exp2f(s[j][1] - m0);
            s[j][2] = exp2f(s[j][2] - m1);
            s[j][3] = exp2f(s[j][3] - m1);
            rs0 += s[j][0] + s[j][1];
            rs1 += s[j][2] + s[j][3];
        }
        rs0 += __shfl_xor_sync(0xffffffffu, rs0, 1);
        rs0 += __shfl_xor_sync(0xffffffffu, rs0, 2);
        rs1 += __shfl_xor_sync(0xffffffffu, rs1, 1);
        rs1 += __shfl_xor_sync(0xffffffffu, rs1, 2);

        l0 = l0 * c0 + rs0;
        l1 = l1 * c1 + rs1;
#pragma unroll
        for (int j = 0; j < 8; j++) {
            o[j][0] *= c0; o[j][1] *= c0;
            o[j][2] *= c1; o[j][3] *= c1;
        }

        // ---- O += P V : 64 keys (bf16x3, P packed in registers) ----
#pragma unroll
        for (int kk = 0; kk < 4; kk++) {
            uint32_t ph[4], pl[4];
            split2(s[2 * kk][0],     s[2 * kk][1],     ph[0], pl[0]);
            split2(s[2 * kk][2],     s[2 * kk][3],     ph[1], pl[1]);
            split2(s[2 * kk + 1][0], s[2 * kk + 1][1], ph[2], pl[2]);
            split2(s[2 * kk + 1][2], s[2 * kk + 1][3], ph[3], pl[3]);
#pragma unroll
            for (int jp = 0; jp < 4; jp++) {
                const uint32_t off =
                    (uint32_t)((kk * 16 + a_row) * ATS + jp * 16 + a_col) * 2;
                uint32_t vh0, vh1, vh2, vh3, vl0, vl1, vl2, vl3;
                LDSM_X4_T(vh0, vh1, vh2, vh3, kb + OVh + off);
                LDSM_X4_T(vl0, vl1, vl2, vl3, kb + OVl + off);
                MMA_BF16(o[2 * jp],     ph[0], ph[1], ph[2], ph[3], vh0, vh1);
                MMA_BF16(o[2 * jp],     ph[0], ph[1], ph[2], ph[3], vl0, vl1);
                MMA_BF16(o[2 * jp],     pl[0], pl[1], pl[2], pl[3], vh0, vh1);
                MMA_BF16(o[2 * jp + 1], ph[0], ph[1], ph[2], ph[3], vh2, vh3);
                MMA_BF16(o[2 * jp + 1], ph[0], ph[1], ph[2], ph[3], vl2, vl3);
                MMA_BF16(o[2 * jp + 1], pl[0], pl[1], pl[2], pl[3], vh2, vh3);
            }
        }
    }

    // ---- epilogue ----
    const float i0 = 1.0f / l0, i1 = 1.0f / l1;
    const int grow = b * SEQ + qt * 128 + 16 * wrp + g;
#pragma unroll
    for (int j = 0; j < 8; j++) {
        const int col = h * 64 + j * 8 + 2 * tig;
        *(float2*)(out + (size_t)grow * EMB + col) =
            make_float2(o[j][0] * i0, o[j][1] * i0);
        *(float2*)(out + (size_t)(grow + 8) * EMB + col) =
            make_float2(o[j][2] * i1, o[j][3] * i1);
    }
#undef KV_ISSUE
}

// ---------------------------------------------------------------------------
extern "C" void kernel_launch(void* const* d_in, const int* in_sizes, int n_in,
                              void* d_out, int out_size)
{
    const float* x    = (const float*)d_in[0];
    const float* w    = (const float*)d_in[1];
    const float* Wqkv = (const float*)d_in[2];
    const float* bqkv = (const float*)d_in[3];
    float* out = (float*)d_out;

    cudaFuncSetAttribute(qkv_gemm,
                         cudaFuncAttributeMaxDynamicSharedMemorySize,
                         GEMM_SMEM_BYTES);
    cudaFuncSetAttribute(attn_bf16,
                         cudaFuncAttributeMaxDynamicSharedMemorySize,
                         ATTN_SMEM_BYTES);

    split_x_kernel<<<MROWS * EMB / 4 / 256, 256>>>((const float4*)x);
    split_w_kernel<<<EMB * QKVN / 4 / 256, 256>>>((const float4*)Wqkv);
    wprep_kernel<<<(BATCH * SEQ + 255) / 256, 256>>>(w);

    dim3 g1(QKVN / 128, MROWS / 128);            // (24, 32)
    qkv_gemm<<<g1, 256, GEMM_SMEM_BYTES>>>(bqkv);

    dim3 g2(SEQ / 128, NHEAD, BATCH);            // (16, 16, 2)
    attn_bf16<<<g2, 256, ATTN_SMEM_BYTES>>>(out);
}

// round 10
// speedup vs baseline: 1.2524x; 1.1735x over previous
#include <cuda_runtime.h>
#include <cuda_bf16.h>
#include <cuda_fp16.h>
#include <math.h>
#include <stdint.h>

// Problem constants
#define BATCH   2
#define SEQ     2048
#define EMB     1024
#define NHEAD   16
#define QKVN    3072
#define MROWS   4096
#define TINY_F  1.17549435e-38f
#define SCALE_Q 0.125f
#define LOG2E   1.4426950408889634f
#define BIGNEG2 -1.3e16f
#define BIGPOS2  1.3e16f

// Global scratch
__device__ __nv_bfloat16 g_x_hi[(size_t)MROWS * EMB];
__device__ __nv_bfloat16 g_x_lo[(size_t)MROWS * EMB];
__device__ __nv_bfloat16 g_w_hi[(size_t)EMB * QKVN];
__device__ __nv_bfloat16 g_w_lo[(size_t)EMB * QKVN];
__device__ __nv_bfloat16 g_qkv_hi[(size_t)MROWS * QKVN];
__device__ __nv_bfloat16 g_qkv_lo[(size_t)MROWS * QKVN];
__device__ __half        g_v[(size_t)MROWS * EMB];      // V as fp16, [row][h*64+d]
__device__ float g_wsc[BATCH * SEQ];   // log2-domain scale
__device__ float g_wvl[BATCH * SEQ];   // log2-domain bias

// ---------------------------------------------------------------------------
// PTX helpers
// ---------------------------------------------------------------------------
#define MMA_BF16(c, a0, a1, a2, a3, b0, b1)                                  \
    asm volatile(                                                            \
        "mma.sync.aligned.m16n8k16.row.col.f32.bf16.bf16.f32 "               \
        "{%0,%1,%2,%3}, {%4,%5,%6,%7}, {%8,%9}, {%0,%1,%2,%3};"              \
        : "+f"((c)[0]), "+f"((c)[1]), "+f"((c)[2]), "+f"((c)[3])             \
        : "r"(a0), "r"(a1), "r"(a2), "r"(a3), "r"(b0), "r"(b1))

#define MMA_FP16(c, a0, a1, a2, a3, b0, b1)                                  \
    asm volatile(                                                            \
        "mma.sync.aligned.m16n8k16.row.col.f32.f16.f16.f32 "                 \
        "{%0,%1,%2,%3}, {%4,%5,%6,%7}, {%8,%9}, {%0,%1,%2,%3};"              \
        : "+f"((c)[0]), "+f"((c)[1]), "+f"((c)[2]), "+f"((c)[3])             \
        : "r"(a0), "r"(a1), "r"(a2), "r"(a3), "r"(b0), "r"(b1))

#define LDSM_X4(r0, r1, r2, r3, a)                                           \
    asm volatile("ldmatrix.sync.aligned.m8n8.x4.shared.b16 {%0,%1,%2,%3}, [%4];" \
        : "=r"(r0), "=r"(r1), "=r"(r2), "=r"(r3) : "r"(a))

#define LDSM_X4_T(r0, r1, r2, r3, a)                                         \
    asm volatile("ldmatrix.sync.aligned.m8n8.x4.trans.shared.b16 {%0,%1,%2,%3}, [%4];" \
        : "=r"(r0), "=r"(r1), "=r"(r2), "=r"(r3) : "r"(a))

#define CPA16(dst_u32, src_ptr)                                              \
    asm volatile("cp.async.cg.shared.global [%0], [%1], 16;"                 \
                 :: "r"(dst_u32), "l"(src_ptr))
#define CPA_COMMIT() asm volatile("cp.async.commit_group;")
#define CPA_WAIT1()  asm volatile("cp.async.wait_group 1;")
#define CPA_WAIT0()  asm volatile("cp.async.wait_group 0;")

__device__ __forceinline__ void split2(float x, float y,
                                       uint32_t& hi, uint32_t& lo)
{
    __nv_bfloat162 h = __floats2bfloat162_rn(x, y);
    float rx = x - __bfloat162float(h.x);
    float ry = y - __bfloat162float(h.y);
    __nv_bfloat162 l = __floats2bfloat162_rn(rx, ry);
    hi = *reinterpret_cast<uint32_t*>(&h);
    lo = *reinterpret_cast<uint32_t*>(&l);
}

__device__ __forceinline__ uint32_t packh2(float x, float y)
{
    __half2 h = __floats2half2_rn(x, y);
    return *reinterpret_cast<uint32_t*>(&h);
}

// ---------------------------------------------------------------------------
// Prep kernels
// ---------------------------------------------------------------------------
__device__ __forceinline__ void split_store(const float4* in, uint2* hi,
                                            uint2* lo, int i)
{
    float4 v = in[i];
    uint2 uh, ul;
    split2(v.x, v.y, uh.x, ul.x);
    split2(v.z, v.w, uh.y, ul.y);
    hi[i] = uh;
    lo[i] = ul;
}

__global__ void split_x_kernel(const float4* __restrict__ in)
{
    int i = blockIdx.x * blockDim.x + threadIdx.x;
    if (i < MROWS * EMB / 4)
        split_store(in, (uint2*)g_x_hi, (uint2*)g_x_lo, i);
}

__global__ void split_w_kernel(const float4* __restrict__ in)
{
    int i = blockIdx.x * blockDim.x + threadIdx.x;
    if (i < EMB * QKVN / 4)
        split_store(in, (uint2*)g_w_hi, (uint2*)g_w_lo, i);
}

__global__ void wprep_kernel(const float* __restrict__ w)
{
    int i = blockIdx.x * blockDim.x + threadIdx.x;
    if (i < BATCH * SEQ) {
        const float v = w[i];
        const bool z = (v == 0.0f), on = (v == 1.0f);
        g_wsc[i] = (z || on) ? 0.0f : SCALE_Q * LOG2E;
        g_wvl[i] = z ? BIGNEG2 : (on ? BIGPOS2 : log2f(v + TINY_F));
    }
}

// ---------------------------------------------------------------------------
// Kernel 1: qkv = x @ W + b, bf16x3 mma. CTA 128x128, BK=32, 256 threads.
// 2-buffer ring, issue-before-wait. Epilogue also writes fp16 V for columns
// in the per-head v-region (col % 192 >= 128; layout is per-head [q|k|v]).
// ---------------------------------------------------------------------------
#define GA_STR 40
#define GB_STR 136
#define GA_H   (128 * GA_STR)
#define GB_H   (32 * GB_STR)
#define GBUF_H (2 * GA_H + 2 * GB_H)
#define GEMM_SMEM_BYTES (2 * GBUF_H * 2)  // 75776 -> 2 CTAs/SM

__global__ void __launch_bounds__(256)
qkv_gemm(const float* __restrict__ bias)
{
    extern __shared__ __nv_bfloat16 sh[];
    const uint32_t sbase = (uint32_t)__cvta_generic_to_shared(sh);

    const int tid  = threadIdx.x;
    const int lane = tid & 31, wid = tid >> 5;
    const int g = lane >> 2, tig = lane & 3;
    const int wr = wid >> 1, wc = wid & 1;
    const int bn = blockIdx.x * 128, bm = blockIdx.y * 128;

    const uint32_t OAh = 0, OAl = GA_H * 2;
    const uint32_t OBh = 2 * GA_H * 2, OBl = (2 * GA_H + GB_H) * 2;
    const uint32_t BUFB = GBUF_H * 2;

    float acc[2][8][4];
#pragma unroll
    for (int mt = 0; mt < 2; mt++)
#pragma unroll
        for (int j = 0; j < 8; j++)
#pragma unroll
            for (int q = 0; q < 4; q++) acc[mt][j][q] = 0.0f;

    const int a_row = (lane & 7) + 8 * ((lane >> 3) & 1);
    const int a_col = 8 * (lane >> 4);
    const int b_row = lane & 15;
    const int b_col = 8 * (lane >> 4);

#define GEMM_ISSUE(buf, kt)                                                  \
    do {                                                                     \
        const uint32_t sb = sbase + (buf) * BUFB;                            \
        _Pragma("unroll")                                                    \
        for (int i = 0; i < 2; i++) {                                        \
            int ch = tid + 256 * i;                                          \
            int r = ch >> 2, sg = ch & 3;                                    \
            size_t go = (size_t)(bm + r) * EMB + (kt) * 32 + sg * 8;         \
            uint32_t d = sb + (uint32_t)(r * GA_STR + sg * 8) * 2;           \
            CPA16(d + OAh, g_x_hi + go);                                     \
            CPA16(d + OAl, g_x_lo + go);                                     \
        }                                                                    \
        _Pragma("unroll")                                                    \
        for (int i = 0; i < 2; i++) {                                        \
            int ch = tid + 256 * i;                                          \
            int r = ch >> 4, sg = ch & 15;                                   \
            size_t go = (size_t)((kt) * 32 + r) * QKVN + bn + sg * 8;        \
            uint32_t d = sb + (uint32_t)(r * GB_STR + sg * 8) * 2;           \
            CPA16(d + OBh, g_w_hi + go);                                     \
            CPA16(d + OBl, g_w_lo + go);                                     \
        }                                                                    \
    } while (0)

    GEMM_ISSUE(0, 0);
    CPA_COMMIT();

    for (int kt = 0; kt < 32; kt++) {
        const int buf = kt & 1;
        if (kt < 31) {
            GEMM_ISSUE(buf ^ 1, kt + 1);
            CPA_COMMIT();
            CPA_WAIT1();
        } else {
            CPA_WAIT0();
        }
        __syncthreads();

        const uint32_t sb = sbase + buf * BUFB;
#pragma unroll
        for (int ks = 0; ks < 2; ks++) {
            const int k0 = ks * 16;
            uint32_t ah[2][4], al[2][4];
#pragma unroll
            for (int mt = 0; mt < 2; mt++) {
                const uint32_t off =
                    (uint32_t)((wr * 32 + mt * 16 + a_row) * GA_STR + k0 + a_col) * 2;
                LDSM_X4(ah[mt][0], ah[mt][1], ah[mt][2], ah[mt][3], sb + OAh + off);
                LDSM_X4(al[mt][0], al[mt][1], al[mt][2], al[mt][3], sb + OAl + off);
            }
#pragma unroll
            for (int jp = 0; jp < 4; jp++) {
                const uint32_t off =
                    (uint32_t)((k0 + b_row) * GB_STR + wc * 64 + jp * 16 + b_col) * 2;
                uint32_t bh0, bh1, bh2, bh3, bl0, bl1, bl2, bl3;
                LDSM_X4_T(bh0, bh1, bh2, bh3, sb + OBh + off);
                LDSM_X4_T(bl0, bl1, bl2, bl3, sb + OBl + off);
#pragma unroll
                for (int mt = 0; mt < 2; mt++) {
                    MMA_BF16(acc[mt][2 * jp], ah[mt][0], ah[mt][1], ah[mt][2], ah[mt][3], bh0, bh1);
                    MMA_BF16(acc[mt][2 * jp], ah[mt][0], ah[mt][1], ah[mt][2], ah[mt][3], bl0, bl1);
                    MMA_BF16(acc[mt][2 * jp], al[mt][0], al[mt][1], al[mt][2], al[mt][3], bh0, bh1);
                    MMA_BF16(acc[mt][2 * jp + 1], ah[mt][0], ah[mt][1], ah[mt][2], ah[mt][3], bh2, bh3);
                    MMA_BF16(acc[mt][2 * jp + 1], ah[mt][0], ah[mt][1], ah[mt][2], ah[mt][3], bl2, bl3);
                    MMA_BF16(acc[mt][2 * jp + 1], al[mt][0], al[mt][1], al[mt][2], al[mt][3], bh2, bh3);
                }
            }
        }
        __syncthreads();
    }

    // Epilogue: hi/lo bf16 everywhere; fp16 V for per-head v-region columns.
#pragma unroll
    for (int mt = 0; mt < 2; mt++) {
        const int row0 = bm + wr * 32 + mt * 16 + g;
#pragma unroll
        for (int j = 0; j < 8; j++) {
            const int col = bn + wc * 64 + j * 8 + 2 * tig;
            const float2 bb = *(const float2*)(bias + col);
            const float v00 = acc[mt][j][0] + bb.x, v01 = acc[mt][j][1] + bb.y;
            const float v10 = acc[mt][j][2] + bb.x, v11 = acc[mt][j][3] + bb.y;
            uint32_t h0, l0, h1, l1;
            split2(v00, v01, h0, l0);
            split2(v10, v11, h1, l1);
            *(uint32_t*)(g_qkv_hi + (size_t)row0 * QKVN + col)       = h0;
            *(uint32_t*)(g_qkv_lo + (size_t)row0 * QKVN + col)       = l0;
            *(uint32_t*)(g_qkv_hi + (size_t)(row0 + 8) * QKVN + col) = h1;
            *(uint32_t*)(g_qkv_lo + (size_t)(row0 + 8) * QKVN + col) = l1;
            // qkv row layout is per-head [q(64) | k(64) | v(64)] blocks of 192.
            // Column pairs never straddle the 64-wide regions (col is even,
            // region boundaries are even), so a per-pair test is exact.
            const int cm = col % 192;
            if (cm >= 128) {
                const int head = col / 192;
                const int vc = head * 64 + (cm - 128);
                *(uint32_t*)(g_v + (size_t)row0 * EMB + vc)       = packh2(v00, v01);
                *(uint32_t*)(g_v + (size_t)(row0 + 8) * EMB + vc) = packh2(v10, v11);
            }
        }
    }
#undef GEMM_ISSUE
}

// ---------------------------------------------------------------------------
// Kernel 2: flash attention. Grid (S/128, H, B), 256 threads, 2 CTAs/SM.
// S = QK^T in bf16x3; PV in single-term fp16 (P, V fp16).
// BQ=128, BN=64, 2-slot KV ring (K hi/lo bf16 + V fp16), exp2 softmax.
// ---------------------------------------------------------------------------
#define ATS      72
#define QTILE_B  (128 * ATS * 2)               // 18432 per array
#define KT64_B   (64 * ATS * 2)                // 9216 per array
#define BQh      0
#define BQl      QTILE_B
#define KVBASE   (2 * QTILE_B)                 // 36864
#define SLOT_B   (3 * KT64_B)                  // 27648 (Khi, Klo, V)
#define OKh      0
#define OKl      KT64_B
#define OV       (2 * KT64_B)
#define ATTN_SMEM_BYTES (KVBASE + 2 * SLOT_B)  // 92160 -> 2 CTAs/SM
#define NKT      (SEQ / 64)                    // 32

__global__ void __launch_bounds__(256, 2)
attn_bf16(float* __restrict__ out)
{
    extern __shared__ char shb[];
    const uint32_t sb = (uint32_t)__cvta_generic_to_shared(shb);

    const int tid  = threadIdx.x;
    const int lane = tid & 31, wrp = tid >> 5;
    const int g = lane >> 2, tig = lane & 3;
    const int qt = blockIdx.x, h = blockIdx.y, b = blockIdx.z;

    const int a_row = (lane & 7) + 8 * ((lane >> 3) & 1);
    const int a_col = 8 * (lane >> 4);
    const int k_row = (lane & 7) + 8 * (lane >> 4);
    const int k_col = 8 * ((lane >> 3) & 1);

#define KV_ISSUE(slot, tt)                                                   \
    do {                                                                     \
        const uint32_t kbase = sb + KVBASE + (uint32_t)(slot) * SLOT_B;      \
        _Pragma("unroll")                                                    \
        for (int i = 0; i < 2; i++) {                                        \
            int ch = tid + 256 * i;                                          \
            int r = ch >> 3, sg = ch & 7;                                    \
            size_t gk = (size_t)(b * SEQ + (tt) * 64 + r) * QKVN + h * 192 + 64 + sg * 8; \
            size_t gv = (size_t)(b * SEQ + (tt) * 64 + r) * EMB + h * 64 + sg * 8; \
            uint32_t d = (uint32_t)(r * ATS + sg * 8) * 2;                   \
            CPA16(kbase + OKh + d, g_qkv_hi + gk);                           \
            CPA16(kbase + OKl + d, g_qkv_lo + gk);                           \
            CPA16(kbase + OV  + d, g_v + gv);                                \
        }                                                                    \
        CPA_COMMIT();                                                        \
    } while (0)

    // ---- prologue: Q (group 0), KV tile 0 (group 1) ----
#pragma unroll
    for (int i = 0; i < 4; i++) {
        const int ch = tid + 256 * i;
        const int r = ch >> 3, sg = ch & 7;
        const size_t go = (size_t)(b * SEQ + qt * 128 + r) * QKVN + h * 192 + sg * 8;
        const uint32_t d = (uint32_t)(r * ATS + sg * 8) * 2;
        CPA16(sb + BQh + d, g_qkv_hi + go);
        CPA16(sb + BQl + d, g_qkv_lo + go);
    }
    CPA_COMMIT();
    KV_ISSUE(0, 0);
    CPA_WAIT1();           // Q landed
    __syncthreads();

    // Q-hi fragments -> registers (loop invariant); Q-lo reloaded per tile
    uint32_t qh[4][4];
#pragma unroll
    for (int kk = 0; kk < 4; kk++) {
        const uint32_t off =
            (uint32_t)((16 * wrp + a_row) * ATS + kk * 16 + a_col) * 2;
        LDSM_X4(qh[kk][0], qh[kk][1], qh[kk][2], qh[kk][3], sb + BQh + off);
    }

    float m0 = -1e30f, m1 = -1e30f, l0 = 0.0f, l1 = 0.0f;
    float o[8][4];
#pragma unroll
    for (int j = 0; j < 8; j++)
        o[j][0] = o[j][1] = o[j][2] = o[j][3] = 0.0f;

    const float* wscp = g_wsc + b * SEQ;
    const float* wvlp = g_wvl + b * SEQ;

    for (int t = 0; t < NKT; t++) {
        const int slot = t & 1;
        CPA_WAIT0();        // tile t landed (sole pending group)
        __syncthreads();    // readers of slot^1 (tile t-1) all done

        if (t + 1 < NKT)
            KV_ISSUE(slot ^ 1, t + 1);

        const uint32_t kb = sb + KVBASE + (uint32_t)slot * SLOT_B;

        // ---- S = Q K^T : 16 q-rows x 64 keys per warp (bf16x3) ----
        float s[8][4];
#pragma unroll
        for (int j = 0; j < 8; j++)
            s[j][0] = s[j][1] = s[j][2] = s[j][3] = 0.0f;

#pragma unroll
        for (int kk = 0; kk < 4; kk++) {
            uint32_t ql0, ql1, ql2, ql3;
            const uint32_t qoff =
                (uint32_t)((16 * wrp + a_row) * ATS + kk * 16 + a_col) * 2;
            LDSM_X4(ql0, ql1, ql2, ql3, sb + BQl + qoff);
#pragma unroll
            for (int jp = 0; jp < 4; jp++) {
                const uint32_t off =
                    (uint32_t)((jp * 16 + k_row) * ATS + kk * 16 + k_col) * 2;
                uint32_t kh0, kh1, kh2, kh3, kl0, kl1, kl2, kl3;
                LDSM_X4(kh0, kh1, kh2, kh3, kb + OKh + off);
                LDSM_X4(kl0, kl1, kl2, kl3, kb + OKl + off);
                MMA_BF16(s[2 * jp],     qh[kk][0], qh[kk][1], qh[kk][2], qh[kk][3], kh0, kh1);
                MMA_BF16(s[2 * jp],     qh[kk][0], qh[kk][1], qh[kk][2], qh[kk][3], kl0, kl1);
                MMA_BF16(s[2 * jp],     ql0, ql1, ql2, ql3, kh0, kh1);
                MMA_BF16(s[2 * jp + 1], qh[kk][0], qh[kk][1], qh[kk][2], qh[kk][3], kh2, kh3);
                MMA_BF16(s[2 * jp + 1], qh[kk][0], qh[kk][1], qh[kk][2], qh[kk][3], kl2, kl3);
                MMA_BF16(s[2 * jp + 1], ql0, ql1, ql2, ql3, kh2, kh3);
            }
        }

        // ---- logit transform (log2 domain) + row max ----
        const int wbase = t * 64;
        float mx0 = -1e30f, mx1 = -1e30f;
#pragma unroll
        for (int j = 0; j < 8; j++) {
            const float2 ws = *(const float2*)&wscp[wbase + j * 8 + 2 * tig];
            const float2 wv = *(const float2*)&wvlp[wbase + j * 8 + 2 * tig];
            s[j][0] = fmaf(s[j][0], ws.x, wv.x);
            s[j][1] = fmaf(s[j][1], ws.y, wv.y);
            s[j][2] = fmaf(s[j][2], ws.x, wv.x);
            s[j][3] = fmaf(s[j][3], ws.y, wv.y);
            mx0 = fmaxf(mx0, fmaxf(s[j][0], s[j][1]));
            mx1 = fmaxf(mx1, fmaxf(s[j][2], s[j][3]));
        }
        mx0 = fmaxf(mx0, __shfl_xor_sync(0xffffffffu, mx0, 1));
        mx0 = fmaxf(mx0, __shfl_xor_sync(0xffffffffu, mx0, 2));
        mx1 = fmaxf(mx1, __shfl_xor_sync(0xffffffffu, mx1, 1));
        mx1 = fmaxf(mx1, __shfl_xor_sync(0xffffffffu, mx1, 2));

        const float mn0 = fmaxf(m0, mx0), mn1 = fmaxf(m1, mx1);
        const float c0 = exp2f(m0 - mn0), c1 = exp2f(m1 - mn1);
        m0 = mn0; m1 = mn1;

        float rs0 = 0.0f, rs1 = 0.0f;
#pragma unroll
        for (int j = 0; j < 8; j++) {
            s[j][0] = exp2f(s[j][0] - m0);
            s[j][1] = exp2f(s[j][1] - m0);
            s[j][2] = exp2f(s[j][2] - m1);
            s[j][3] = exp2f(s[j][3] - m1);
            rs0 += s[j][0] + s[j][1];
            rs1 += s[j][2] + s[j][3];
        }
        rs0 += __shfl_xor_sync(0xffffffffu, rs0, 1);
        rs0 += __shfl_xor_sync(0xffffffffu, rs0, 2);
        rs1 += __shfl_xor_sync(0xffffffffu, rs1, 1);
        rs1 += __shfl_xor_sync(0xffffffffu, rs1, 2);

        l0 = l0 * c0 + rs0;
        l1 = l1 * c1 + rs1;
#pragma unroll
        for (int j = 0; j < 8; j++) {
            o[j][0] *= c0; o[j][1] *= c0;
            o[j][2] *= c1; o[j][3] *= c1;
        }

        // ---- O += P V : single-term fp16 (P, V fp16) ----
#pragma unroll
        for (int kk = 0; kk < 4; kk++) {
            uint32_t ph[4];
            ph[0] = packh2(s[2 * kk][0],     s[2 * kk][1]);
            ph[1] = packh2(s[2 * kk][2],     s[2 * kk][3]);
            ph[2] = packh2(s[2 * kk + 1][0], s[2 * kk + 1][1]);
            ph[3] = packh2(s[2 * kk + 1][2], s[2 * kk + 1][3]);
#pragma unroll
            for (int jp = 0; jp < 4; jp++) {
                const uint32_t off =
                    (uint32_t)((kk * 16 + a_row) * ATS + jp * 16 + a_col) * 2;
                uint32_t vh0, vh1, vh2, vh3;
                LDSM_X4_T(vh0, vh1, vh2, vh3, kb + OV + off);
                MMA_FP16(o[2 * jp],     ph[0], ph[1], ph[2], ph[3], vh0, vh1);
                MMA_FP16(o[2 * jp + 1], ph[0], ph[1], ph[2], ph[3], vh2, vh3);
            }
        }
    }

    // ---- epilogue ----
    const float i0 = 1.0f / l0, i1 = 1.0f / l1;
    const int grow = b * SEQ + qt * 128 + 16 * wrp + g;
#pragma unroll
    for (int j = 0; j < 8; j++) {
        const int col = h * 64 + j * 8 + 2 * tig;
        *(float2*)(out + (size_t)grow * EMB + col) =
            make_float2(o[j][0] * i0, o[j][1] * i0);
        *(float2*)(out + (size_t)(grow + 8) * EMB + col) =
            make_float2(o[j][2] * i1, o[j][3] * i1);
    }
#undef KV_ISSUE
}

// ---------------------------------------------------------------------------
extern "C" void kernel_launch(void* const* d_in, const int* in_sizes, int n_in,
                              void* d_out, int out_size)
{
    const float* x    = (const float*)d_in[0];
    const float* w    = (const float*)d_in[1];
    const float* Wqkv = (const float*)d_in[2];
    const float* bqkv = (const float*)d_in[3];
    float* out = (float*)d_out;

    cudaFuncSetAttribute(qkv_gemm,
                         cudaFuncAttributeMaxDynamicSharedMemorySize,
                         GEMM_SMEM_BYTES);
    cudaFuncSetAttribute(attn_bf16,
                         cudaFuncAttributeMaxDynamicSharedMemorySize,
                         ATTN_SMEM_BYTES);

    split_x_kernel<<<MROWS * EMB / 4 / 256, 256>>>((const float4*)x);
    split_w_kernel<<<EMB * QKVN / 4 / 256, 256>>>((const float4*)Wqkv);
    wprep_kernel<<<(BATCH * SEQ + 255) / 256, 256>>>(w);

    dim3 g1(QKVN / 128, MROWS / 128);            // (24, 32)
    qkv_gemm<<<g1, 256, GEMM_SMEM_BYTES>>>(bqkv);

    dim3 g2(SEQ / 128, NHEAD, BATCH);            // (16, 16, 2)
    attn_bf16<<<g2, 256, ATTN_SMEM_BYTES>>>(out);
}